// round 7
// baseline (speedup 1.0000x reference)
#include <cuda_runtime.h>

#define B_ROWS 8192
#define KNUM   50
#define NKG    200000

#define BK 32
#define STAGES 3
#define A_STRIDE 36              // 36 ≡ 4 (mod 32): gid*4+tig covers all banks
#define A_TILE_W (128 * A_STRIDE)

// Scratch (static __device__ arrays — no runtime allocation)
__device__ float g_table[(size_t)NKG * 64];
__device__ float g_h1[B_ROWS * 128];
__device__ float g_h2[B_ROWS * 512];
__device__ float g_h3[B_ROWS * 128];
__device__ float g_h4[B_ROWS * 64];
__device__ float g_know[B_ROWS * 64];
// Pre-converted (tf32-rounded) weights, packed:
// [0]=Wkg 4096, [4096]=W1a 65536, [69632]=W1b 65536, [135168]=W1c 65536,
// [200704]=W1d 8192, [208896]=W2 65536  -> total 274432 floats
__device__ float g_wbuf[274432];

__device__ __forceinline__ unsigned f2tf(float f) {
    unsigned u;
    asm("cvt.rna.tf32.f32 %0, %1;" : "=r"(u) : "f"(f));
    return u;
}

__device__ __forceinline__ void mma8(float* c, const unsigned* a, const unsigned* b) {
    asm volatile(
        "mma.sync.aligned.m16n8k8.row.col.f32.tf32.tf32.f32 "
        "{%0,%1,%2,%3}, {%4,%5,%6,%7}, {%8,%9}, {%0,%1,%2,%3};"
        : "+f"(c[0]), "+f"(c[1]), "+f"(c[2]), "+f"(c[3])
        : "r"(a[0]), "r"(a[1]), "r"(a[2]), "r"(a[3]), "r"(b[0]), "r"(b[1]));
}

__device__ __forceinline__ void cpasync16(unsigned dst, const void* src) {
    asm volatile("cp.async.cg.shared.global [%0], [%1], 16;" :: "r"(dst), "l"(src));
}
__device__ __forceinline__ void cpcommit() {
    asm volatile("cp.async.commit_group;" ::: "memory");
}
__device__ __forceinline__ void cpwait1() {
    asm volatile("cp.async.wait_group 1;" ::: "memory");
}

// Round a weight matrix to tf32 (RNA) once; downstream raw reads are exact.
__global__ __launch_bounds__(256) void cvt_w(const float* __restrict__ src,
                                             float* __restrict__ dst, int n4)
{
    int i = blockIdx.x * 256 + threadIdx.x;
    if (i < n4) {
        float4 v = ((const float4*)src)[i];
        uint4 o;
        o.x = f2tf(v.x); o.y = f2tf(v.y); o.z = f2tf(v.z); o.w = f2tf(v.w);
        ((uint4*)dst)[i] = o;
    }
}

// ---------------------------------------------------------------------------
// TF32 tensor-core GEMM, cp.async 3-stage pipeline.
// MT m16-tiles/warp along M, NWN warps along N (NWM=8/NWN); BM=128, BN=NWN*32.
// CVTA: RNA-convert A fragments at read (external fp32 A).
//       Otherwise A is read raw (must already be tf32-rounded).
// W (B operand) is always read raw (pre-rounded by cvt_w).
// RELU optional; EPIADD: += addv after ReLU; ROUND: tf32-round stores.
// Requires N % BN == 0, K % 32 == 0, K >= 64; M guarded.
// ---------------------------------------------------------------------------
template <int MT, int NWN, bool RELU, bool EPIADD, bool CVTA, bool ROUND>
__global__ __launch_bounds__(256) void tgemm(const float* __restrict__ A,
                                             const float* __restrict__ W,
                                             const float* __restrict__ bias,
                                             const float* __restrict__ addv,
                                             float* __restrict__ C,
                                             int M, int N, int K)
{
    constexpr int NWM      = 8 / NWN;
    constexpr int BN       = NWN * 32;
    constexpr int B_STRIDE = BN + 8;            // ≡ 8 (mod 32)
    constexpr int B_TILE_W = BK * B_STRIDE;
    constexpr int STAGE_W  = A_TILE_W + B_TILE_W;
    constexpr int BLOADS   = BN / 32;

    extern __shared__ float sm[];
    const unsigned smBase = (unsigned)__cvta_generic_to_shared(sm);

    const int t      = threadIdx.x;
    const int lane   = t & 31;
    const int wid    = t >> 5;
    const int warp_m = wid % NWM;
    const int warp_n = wid / NWM;
    const int gid    = lane >> 2;
    const int tig    = lane & 3;
    const int rowBase = blockIdx.x * 128;
    const int colBase = blockIdx.y * BN;

    const int ntiles = K / BK;

    auto issueTile = [&](int tile, int stage) {
        const int k0 = tile * BK;
        const unsigned sOff = smBase + stage * (STAGE_W * 4);
#pragma unroll
        for (int p = 0; p < 4; p++) {           // A: 1024 float4s
            int v = t + p * 256;
            int row = v >> 3, seg = v & 7;
            if (rowBase + row < M) {
                unsigned dst = sOff + (row * A_STRIDE + seg * 4) * 4;
                cpasync16(dst, A + (size_t)(rowBase + row) * K + k0 + seg * 4);
            }
        }
#pragma unroll
        for (int p = 0; p < BLOADS; p++) {      // B: 8*BN float4s
            int v = t + p * 256;
            int kk = v / (BN / 4), seg = v % (BN / 4);
            unsigned dst = sOff + (A_TILE_W + kk * B_STRIDE + seg * 4) * 4;
            cpasync16(dst, W + (size_t)(k0 + kk) * N + colBase + seg * 4);
        }
        cpcommit();
    };

    float acc[MT][4][4];
#pragma unroll
    for (int i = 0; i < MT; i++)
#pragma unroll
        for (int j = 0; j < 4; j++)
#pragma unroll
            for (int c = 0; c < 4; c++) acc[i][j][c] = 0.f;

    issueTile(0, 0);
    issueTile(1, 1);

    for (int it = 0; it < ntiles; it++) {
        cpwait1();
        __syncthreads();

        int nxt = it + STAGES - 1;
        if (nxt < ntiles) issueTile(nxt, nxt % STAGES);
        else cpcommit();

        const float* sA = sm + (it % STAGES) * STAGE_W;
        const float* sB = sA + A_TILE_W;

#pragma unroll
        for (int ks = 0; ks < 4; ks++) {
            unsigned af[MT][4], bf[4][2];
#pragma unroll
            for (int i2 = 0; i2 < MT; i2++) {
                int mt = warp_m * MT + i2;
                const float* p = sA + (mt * 16 + gid) * A_STRIDE + ks * 8 + tig;
                if (CVTA) {
                    af[i2][0] = f2tf(p[0]);
                    af[i2][1] = f2tf(p[8 * A_STRIDE]);
                    af[i2][2] = f2tf(p[4]);
                    af[i2][3] = f2tf(p[8 * A_STRIDE + 4]);
                } else {
                    const unsigned* q = (const unsigned*)p;
                    af[i2][0] = q[0];
                    af[i2][1] = q[8 * A_STRIDE];
                    af[i2][2] = q[4];
                    af[i2][3] = q[8 * A_STRIDE + 4];
                }
            }
#pragma unroll
            for (int j = 0; j < 4; j++) {
                int nt = warp_n * 4 + j;
                const unsigned* p = (const unsigned*)sB
                    + (ks * 8 + tig) * B_STRIDE + nt * 8 + gid;
                bf[j][0] = p[0];
                bf[j][1] = p[4 * B_STRIDE];
            }
#pragma unroll
            for (int i2 = 0; i2 < MT; i2++)
#pragma unroll
                for (int j = 0; j < 4; j++)
                    mma8(acc[i2][j], af[i2], bf[j]);
        }
    }

    // Epilogue: c0,c1 at (row, tig*2+{0,1}); c2,c3 at row+8.
#pragma unroll
    for (int i = 0; i < MT; i++) {
        int row0 = rowBase + (warp_m * MT + i) * 16 + gid;
#pragma unroll
        for (int j = 0; j < 4; j++) {
            int col = colBase + warp_n * 32 + j * 8 + tig * 2;
            float2 bv = *(const float2*)(bias + col);
#pragma unroll
            for (int h = 0; h < 2; h++) {
                int row = row0 + h * 8;
                if (row < M) {
                    float2 o = make_float2(acc[i][j][2 * h]     + bv.x,
                                           acc[i][j][2 * h + 1] + bv.y);
                    if (RELU) { o.x = fmaxf(o.x, 0.f); o.y = fmaxf(o.y, 0.f); }
                    if (EPIADD) {
                        float2 av = *(const float2*)(addv + (size_t)row * N + col);
                        o.x += av.x; o.y += av.y;
                    }
                    if (ROUND) {
                        o.x = __uint_as_float(f2tf(o.x));
                        o.y = __uint_as_float(f2tf(o.y));
                    }
                    *(float2*)(C + (size_t)row * N + col) = o;
                }
            }
        }
    }
}

// ---------------------------------------------------------------------------
// Masked gather-sum over precomputed table: one warp per batch row.
// ---------------------------------------------------------------------------
__global__ __launch_bounds__(256) void gather_sum(const int* __restrict__ idx,
                                                  const int* __restrict__ mask)
{
    int w    = (blockIdx.x * 256 + threadIdx.x) >> 5;
    int lane = threadIdx.x & 31;
    if (w >= B_ROWS) return;

    const int* ib = idx  + w * KNUM;
    const int* mb = mask + w * KNUM;

    float2 acc = make_float2(0.f, 0.f);
#pragma unroll 5
    for (int k = 0; k < KNUM; k++) {
        int m = __ldg(&mb[k]);
        if (m) {
            int id   = __ldg(&ib[k]);
            float2 v = *(const float2*)(g_table + (size_t)id * 64 + lane * 2);
            acc.x += v.x;
            acc.y += v.y;
        }
    }
    *(float2*)(g_know + w * 64 + lane * 2) = acc;
}

// ---------------------------------------------------------------------------
extern "C" void kernel_launch(void* const* d_in, const int* in_sizes, int n_in,
                              void* d_out, int out_size)
{
    const float* x   = (const float*)d_in[0];
    const float* kg  = (const float*)d_in[1];
    const int*   idx = (const int*)d_in[2];
    const int*   msk = (const int*)d_in[3];
    const float* Wkg = (const float*)d_in[4];
    const float* bkg = (const float*)d_in[5];
    const float* W1a = (const float*)d_in[6];
    const float* b1a = (const float*)d_in[7];
    const float* W1b = (const float*)d_in[8];
    const float* b1b = (const float*)d_in[9];
    const float* W1c = (const float*)d_in[10];
    const float* b1c = (const float*)d_in[11];
    const float* W1d = (const float*)d_in[12];
    const float* b1d = (const float*)d_in[13];
    const float* W2  = (const float*)d_in[14];
    const float* b2  = (const float*)d_in[15];
    float* out = (float*)d_out;

    float *table, *h1, *h2, *h3, *h4, *know, *wbuf;
    cudaGetSymbolAddress((void**)&table, g_table);
    cudaGetSymbolAddress((void**)&h1, g_h1);
    cudaGetSymbolAddress((void**)&h2, g_h2);
    cudaGetSymbolAddress((void**)&h3, g_h3);
    cudaGetSymbolAddress((void**)&h4, g_h4);
    cudaGetSymbolAddress((void**)&know, g_know);
    cudaGetSymbolAddress((void**)&wbuf, g_wbuf);

    float* cWkg = wbuf;            // 4096
    float* cW1a = wbuf + 4096;     // 65536
    float* cW1b = wbuf + 69632;    // 65536
    float* cW1c = wbuf + 135168;   // 65536
    float* cW1d = wbuf + 200704;   // 8192
    float* cW2  = wbuf + 208896;   // 65536

    const int smemA = STAGES * (A_TILE_W + 32 * 72) * 4;    //  82,944 B (BN=64)
    const int smemB = STAGES * (A_TILE_W + 32 * 136) * 4;   // 107,520 B (BN=128)

    cudaFuncSetAttribute(tgemm<2, 2, true, false, true, false>,
                         cudaFuncAttributeMaxDynamicSharedMemorySize, smemA);
    cudaFuncSetAttribute(tgemm<2, 2, true, true, false, true>,
                         cudaFuncAttributeMaxDynamicSharedMemorySize, smemA);
    cudaFuncSetAttribute(tgemm<4, 4, true, false, true, true>,
                         cudaFuncAttributeMaxDynamicSharedMemorySize, smemB);
    cudaFuncSetAttribute(tgemm<4, 4, true, false, false, true>,
                         cudaFuncAttributeMaxDynamicSharedMemorySize, smemB);
    cudaFuncSetAttribute(tgemm<4, 4, false, false, false, false>,
                         cudaFuncAttributeMaxDynamicSharedMemorySize, smemB);

    dim3 blk(256);

    // 0) pre-round all weights to tf32 (RNA), once per launch
    cvt_w<<<4,   blk>>>(Wkg, cWkg, 1024);
    cvt_w<<<64,  blk>>>(W1a, cW1a, 16384);
    cvt_w<<<64,  blk>>>(W1b, cW1b, 16384);
    cvt_w<<<64,  blk>>>(W1c, cW1c, 16384);
    cvt_w<<<8,   blk>>>(W1d, cW1d, 2048);
    cvt_w<<<64,  blk>>>(W2,  cW2,  16384);

    // 1) knowledge table: T = relu(kg @ Wkg + bkg)   [200000, 64]
    tgemm<2, 2, true, false, true, false><<<dim3((NKG + 127) / 128, 1), blk, smemA>>>(
        kg, cWkg, bkg, nullptr, table, NKG, 64, 64);

    // 2) masked gather-sum over table (L2-hot)
    gather_sum<<<(B_ROWS * 32) / 256, blk>>>(idx, msk);

    // 3) dense MLP chain (intermediates tf32-rounded at store)
    tgemm<4, 4, true, false, true, true><<<dim3(64, 1), blk, smemB>>>(
        x,  cW1a, b1a, nullptr, h1, B_ROWS, 128, 512);
    tgemm<4, 4, true, false, false, true><<<dim3(64, 4), blk, smemB>>>(
        h1, cW1b, b1b, nullptr, h2, B_ROWS, 512, 128);
    tgemm<4, 4, true, false, false, true><<<dim3(64, 1), blk, smemB>>>(
        h2, cW1c, b1c, nullptr, h3, B_ROWS, 128, 512);
    // h4 = tf32round( relu(h3 @ W1d + b1d) + knowledge )
    tgemm<2, 2, true, true, false, true><<<dim3(64, 1), blk, smemA>>>(
        h3, cW1d, b1d, know, h4, B_ROWS, 64, 128);

    // 4) out = h4 @ W2 + b2   (full fp32 epilogue)
    tgemm<4, 4, false, false, false, false><<<dim3(64, 8), blk, smemB>>>(
        h4, cW2, b2, nullptr, out, B_ROWS, 1024, 64);
}

// round 10
// speedup vs baseline: 1.0401x; 1.0401x over previous
#include <cuda_runtime.h>

#define B_ROWS 8192
#define KNUM   50
#define NKG    200000

#define BK 32
#define STAGES 3
#define A_STRIDE 36              // 36 ≡ 4 (mod 32): gid*4+tig covers all banks
#define A_TILE_W (128 * A_STRIDE)

// Scratch (static __device__ arrays — no runtime allocation)
__device__ float g_table[(size_t)NKG * 64];
__device__ float g_h1[B_ROWS * 128];
__device__ float g_h2[B_ROWS * 512];
__device__ float g_h3[B_ROWS * 128];
__device__ float g_h4[B_ROWS * 64];
__device__ float g_know[B_ROWS * 64];
// Pre-converted (tf32-rounded) weights, packed:
// [0]=Wkg 4096, [4096]=W1a 65536, [69632]=W1b 65536, [135168]=W1c 65536,
// [200704]=W1d 8192, [208896]=W2 65536  -> total 274432 floats
__device__ float g_wbuf[274432];

__device__ __forceinline__ unsigned f2tf(float f) {
    unsigned u;
    asm("cvt.rna.tf32.f32 %0, %1;" : "=r"(u) : "f"(f));
    return u;
}

__device__ __forceinline__ void mma8(float* c, const unsigned* a, const unsigned* b) {
    asm volatile(
        "mma.sync.aligned.m16n8k8.row.col.f32.tf32.tf32.f32 "
        "{%0,%1,%2,%3}, {%4,%5,%6,%7}, {%8,%9}, {%0,%1,%2,%3};"
        : "+f"(c[0]), "+f"(c[1]), "+f"(c[2]), "+f"(c[3])
        : "r"(a[0]), "r"(a[1]), "r"(a[2]), "r"(a[3]), "r"(b[0]), "r"(b[1]));
}

__device__ __forceinline__ void cpasync16(unsigned dst, const void* src) {
    asm volatile("cp.async.cg.shared.global [%0], [%1], 16;" :: "r"(dst), "l"(src));
}
__device__ __forceinline__ void cpcommit() {
    asm volatile("cp.async.commit_group;" ::: "memory");
}
__device__ __forceinline__ void cpwait1() {
    asm volatile("cp.async.wait_group 1;" ::: "memory");
}

// ---------------------------------------------------------------------------
// Single-launch weight pre-rounding: all 6 matrices, segment dispatch.
// Total 68608 float4s.
// ---------------------------------------------------------------------------
__global__ __launch_bounds__(256) void cvt_all(const float* __restrict__ Wkg,
                                               const float* __restrict__ W1a,
                                               const float* __restrict__ W1b,
                                               const float* __restrict__ W1c,
                                               const float* __restrict__ W1d,
                                               const float* __restrict__ W2,
                                               float* __restrict__ dst)
{
    int i = blockIdx.x * 256 + threadIdx.x;
    if (i >= 68608) return;
    const float4* s;
    int l;
    if      (i < 1024)  { s = (const float4*)Wkg; l = i; }
    else if (i < 17408) { s = (const float4*)W1a; l = i - 1024; }
    else if (i < 33792) { s = (const float4*)W1b; l = i - 17408; }
    else if (i < 50176) { s = (const float4*)W1c; l = i - 33792; }
    else if (i < 52224) { s = (const float4*)W1d; l = i - 50176; }
    else                { s = (const float4*)W2;  l = i - 52224; }
    float4 v = s[l];
    uint4 o;
    o.x = f2tf(v.x); o.y = f2tf(v.y); o.z = f2tf(v.z); o.w = f2tf(v.w);
    ((uint4*)dst)[i] = o;
}

// ---------------------------------------------------------------------------
// TF32 tensor-core GEMM, cp.async 3-stage pipeline. (unchanged from R7)
// ---------------------------------------------------------------------------
template <int MT, int NWN, bool RELU, bool EPIADD, bool CVTA, bool ROUND>
__global__ __launch_bounds__(256) void tgemm(const float* __restrict__ A,
                                             const float* __restrict__ W,
                                             const float* __restrict__ bias,
                                             const float* __restrict__ addv,
                                             float* __restrict__ C,
                                             int M, int N, int K)
{
    constexpr int NWM      = 8 / NWN;
    constexpr int BN       = NWN * 32;
    constexpr int B_STRIDE = BN + 8;            // ≡ 8 (mod 32)
    constexpr int B_TILE_W = BK * B_STRIDE;
    constexpr int STAGE_W  = A_TILE_W + B_TILE_W;
    constexpr int BLOADS   = BN / 32;

    extern __shared__ float sm[];
    const unsigned smBase = (unsigned)__cvta_generic_to_shared(sm);

    const int t      = threadIdx.x;
    const int lane   = t & 31;
    const int wid    = t >> 5;
    const int warp_m = wid % NWM;
    const int warp_n = wid / NWM;
    const int gid    = lane >> 2;
    const int tig    = lane & 3;
    const int rowBase = blockIdx.x * 128;
    const int colBase = blockIdx.y * BN;

    const int ntiles = K / BK;

    auto issueTile = [&](int tile, int stage) {
        const int k0 = tile * BK;
        const unsigned sOff = smBase + stage * (STAGE_W * 4);
#pragma unroll
        for (int p = 0; p < 4; p++) {           // A: 1024 float4s
            int v = t + p * 256;
            int row = v >> 3, seg = v & 7;
            if (rowBase + row < M) {
                unsigned dst = sOff + (row * A_STRIDE + seg * 4) * 4;
                cpasync16(dst, A + (size_t)(rowBase + row) * K + k0 + seg * 4);
            }
        }
#pragma unroll
        for (int p = 0; p < BLOADS; p++) {      // B: 8*BN float4s
            int v = t + p * 256;
            int kk = v / (BN / 4), seg = v % (BN / 4);
            unsigned dst = sOff + (A_TILE_W + kk * B_STRIDE + seg * 4) * 4;
            cpasync16(dst, W + (size_t)(k0 + kk) * N + colBase + seg * 4);
        }
        cpcommit();
    };

    float acc[MT][4][4];
#pragma unroll
    for (int i = 0; i < MT; i++)
#pragma unroll
        for (int j = 0; j < 4; j++)
#pragma unroll
            for (int c = 0; c < 4; c++) acc[i][j][c] = 0.f;

    issueTile(0, 0);
    issueTile(1, 1);

    for (int it = 0; it < ntiles; it++) {
        cpwait1();
        __syncthreads();

        int nxt = it + STAGES - 1;
        if (nxt < ntiles) issueTile(nxt, nxt % STAGES);
        else cpcommit();

        const float* sA = sm + (it % STAGES) * STAGE_W;
        const float* sB = sA + A_TILE_W;

#pragma unroll
        for (int ks = 0; ks < 4; ks++) {
            unsigned af[MT][4], bf[4][2];
#pragma unroll
            for (int i2 = 0; i2 < MT; i2++) {
                int mt = warp_m * MT + i2;
                const float* p = sA + (mt * 16 + gid) * A_STRIDE + ks * 8 + tig;
                if (CVTA) {
                    af[i2][0] = f2tf(p[0]);
                    af[i2][1] = f2tf(p[8 * A_STRIDE]);
                    af[i2][2] = f2tf(p[4]);
                    af[i2][3] = f2tf(p[8 * A_STRIDE + 4]);
                } else {
                    const unsigned* q = (const unsigned*)p;
                    af[i2][0] = q[0];
                    af[i2][1] = q[8 * A_STRIDE];
                    af[i2][2] = q[4];
                    af[i2][3] = q[8 * A_STRIDE + 4];
                }
            }
#pragma unroll
            for (int j = 0; j < 4; j++) {
                int nt = warp_n * 4 + j;
                const unsigned* p = (const unsigned*)sB
                    + (ks * 8 + tig) * B_STRIDE + nt * 8 + gid;
                bf[j][0] = p[0];
                bf[j][1] = p[4 * B_STRIDE];
            }
#pragma unroll
            for (int i2 = 0; i2 < MT; i2++)
#pragma unroll
                for (int j = 0; j < 4; j++)
                    mma8(acc[i2][j], af[i2], bf[j]);
        }
    }

    // Epilogue
#pragma unroll
    for (int i = 0; i < MT; i++) {
        int row0 = rowBase + (warp_m * MT + i) * 16 + gid;
#pragma unroll
        for (int j = 0; j < 4; j++) {
            int col = colBase + warp_n * 32 + j * 8 + tig * 2;
            float2 bv = *(const float2*)(bias + col);
#pragma unroll
            for (int h = 0; h < 2; h++) {
                int row = row0 + h * 8;
                if (row < M) {
                    float2 o = make_float2(acc[i][j][2 * h]     + bv.x,
                                           acc[i][j][2 * h + 1] + bv.y);
                    if (RELU) { o.x = fmaxf(o.x, 0.f); o.y = fmaxf(o.y, 0.f); }
                    if (EPIADD) {
                        float2 av = *(const float2*)(addv + (size_t)row * N + col);
                        o.x += av.x; o.y += av.y;
                    }
                    if (ROUND) {
                        o.x = __uint_as_float(f2tf(o.x));
                        o.y = __uint_as_float(f2tf(o.y));
                    }
                    *(float2*)(C + (size_t)row * N + col) = o;
                }
            }
        }
    }
}

// ---------------------------------------------------------------------------
// Masked gather-sum over precomputed table: one warp per batch row.
// ---------------------------------------------------------------------------
__global__ __launch_bounds__(256) void gather_sum(const int* __restrict__ idx,
                                                  const int* __restrict__ mask)
{
    int w    = (blockIdx.x * 256 + threadIdx.x) >> 5;
    int lane = threadIdx.x & 31;
    if (w >= B_ROWS) return;

    const int* ib = idx  + w * KNUM;
    const int* mb = mask + w * KNUM;

    float2 acc = make_float2(0.f, 0.f);
#pragma unroll 5
    for (int k = 0; k < KNUM; k++) {
        int m = __ldg(&mb[k]);
        if (m) {
            int id   = __ldg(&ib[k]);
            float2 v = *(const float2*)(g_table + (size_t)id * 64 + lane * 2);
            acc.x += v.x;
            acc.y += v.y;
        }
    }
    *(float2*)(g_know + w * 64 + lane * 2) = acc;
}

// ---------------------------------------------------------------------------
extern "C" void kernel_launch(void* const* d_in, const int* in_sizes, int n_in,
                              void* d_out, int out_size)
{
    const float* x   = (const float*)d_in[0];
    const float* kg  = (const float*)d_in[1];
    const int*   idx = (const int*)d_in[2];
    const int*   msk = (const int*)d_in[3];
    const float* Wkg = (const float*)d_in[4];
    const float* bkg = (const float*)d_in[5];
    const float* W1a = (const float*)d_in[6];
    const float* b1a = (const float*)d_in[7];
    const float* W1b = (const float*)d_in[8];
    const float* b1b = (const float*)d_in[9];
    const float* W1c = (const float*)d_in[10];
    const float* b1c = (const float*)d_in[11];
    const float* W1d = (const float*)d_in[12];
    const float* b1d = (const float*)d_in[13];
    const float* W2  = (const float*)d_in[14];
    const float* b2  = (const float*)d_in[15];
    float* out = (float*)d_out;

    float *table, *h1, *h2, *h3, *h4, *know, *wbuf;
    cudaGetSymbolAddress((void**)&table, g_table);
    cudaGetSymbolAddress((void**)&h1, g_h1);
    cudaGetSymbolAddress((void**)&h2, g_h2);
    cudaGetSymbolAddress((void**)&h3, g_h3);
    cudaGetSymbolAddress((void**)&h4, g_h4);
    cudaGetSymbolAddress((void**)&know, g_know);
    cudaGetSymbolAddress((void**)&wbuf, g_wbuf);

    float* cWkg = wbuf;            // 4096
    float* cW1a = wbuf + 4096;     // 65536
    float* cW1b = wbuf + 69632;    // 65536
    float* cW1c = wbuf + 135168;   // 65536
    float* cW1d = wbuf + 200704;   // 8192
    float* cW2  = wbuf + 208896;   // 65536

    const int smemA = STAGES * (A_TILE_W + 32 * 72) * 4;    //  82,944 B (BN=64)
    const int smemB = STAGES * (A_TILE_W + 32 * 136) * 4;   // 107,520 B (BN=128)

    cudaFuncSetAttribute(tgemm<2, 2, true, false, true, false>,
                         cudaFuncAttributeMaxDynamicSharedMemorySize, smemA);
    cudaFuncSetAttribute(tgemm<2, 2, true, true, false, true>,
                         cudaFuncAttributeMaxDynamicSharedMemorySize, smemA);
    cudaFuncSetAttribute(tgemm<4, 4, true, false, true, true>,
                         cudaFuncAttributeMaxDynamicSharedMemorySize, smemB);
    cudaFuncSetAttribute(tgemm<4, 4, true, false, false, true>,
                         cudaFuncAttributeMaxDynamicSharedMemorySize, smemB);
    cudaFuncSetAttribute(tgemm<4, 4, false, false, false, false>,
                         cudaFuncAttributeMaxDynamicSharedMemorySize, smemB);

    // Fork/join resources (host objects, created once; GPU work is identical
    // every call — determinism preserved)
    static cudaStream_t sKnow = nullptr;
    static cudaEvent_t  eFork = nullptr, eJoin = nullptr;
    if (!sKnow) {
        cudaStreamCreateWithFlags(&sKnow, cudaStreamNonBlocking);
        cudaEventCreateWithFlags(&eFork, cudaEventDisableTiming);
        cudaEventCreateWithFlags(&eJoin, cudaEventDisableTiming);
    }

    dim3 blk(256);

    // 0) one-shot weight pre-rounding (68608 float4s)
    cvt_all<<<268, blk>>>(Wkg, W1a, W1b, W1c, W1d, W2, wbuf);

    // ---- fork: knowledge branch on side stream ----
    cudaEventRecord(eFork, 0);
    cudaStreamWaitEvent(sKnow, eFork, 0);

    // 1) knowledge table: T = relu(kg @ Wkg + bkg)   [200000, 64]
    tgemm<2, 2, true, false, true, false>
        <<<dim3((NKG + 127) / 128, 1), blk, smemA, sKnow>>>(
        kg, cWkg, bkg, nullptr, table, NKG, 64, 64);
    // 2) masked gather-sum over table (L2-hot)
    gather_sum<<<(B_ROWS * 32) / 256, blk, 0, sKnow>>>(idx, msk);
    cudaEventRecord(eJoin, sKnow);

    // ---- main stream: dense MLP chain (overlaps knowledge branch) ----
    tgemm<4, 4, true, false, true, true><<<dim3(64, 1), blk, smemB>>>(
        x,  cW1a, b1a, nullptr, h1, B_ROWS, 128, 512);
    tgemm<4, 4, true, false, false, true><<<dim3(64, 4), blk, smemB>>>(
        h1, cW1b, b1b, nullptr, h2, B_ROWS, 512, 128);
    tgemm<4, 4, true, false, false, true><<<dim3(64, 1), blk, smemB>>>(
        h2, cW1c, b1c, nullptr, h3, B_ROWS, 128, 512);

    // ---- join: h4 needs knowledge ----
    cudaStreamWaitEvent(0, eJoin, 0);
    // h4 = tf32round( relu(h3 @ W1d + b1d) + knowledge )
    tgemm<2, 2, true, true, false, true><<<dim3(64, 1), blk, smemA>>>(
        h3, cW1d, b1d, know, h4, B_ROWS, 64, 128);

    // 4) out = h4 @ W2 + b2   (full fp32 epilogue)
    tgemm<4, 4, false, false, false, false><<<dim3(64, 8), blk, smemB>>>(
        h4, cW2, b2, nullptr, out, B_ROWS, 1024, 64);
}